// round 9
// baseline (speedup 1.0000x reference)
#include <cuda_runtime.h>
#include <cstdint>

// Problem shape (fixed by reference setup_inputs)
#define B_   16
#define Y_   32
#define HW_  65536                   // H*W
#define NPIX (B_ * HW_)              // 1048576
#define THREADS 512
#define PPT 8                        // pixels per thread
#define SPAN (THREADS * PPT)         // 4096 contiguous pixels per block
#define GRID (NPIX / SPAN)           // 256 blocks, single wave at 2/SM
#define STAGES 6
#define ROW_BYTES (SPAN * 4)         // 16 KB contiguous per (b,y) row chunk
#define SMEM_BYTES (1024 + STAGES * ROW_BYTES)   // 97 KB
#define DIST_IND 7.0f

__device__ double g_partials[GRID];
__device__ unsigned int g_count = 0;

__device__ __forceinline__ uint32_t smem_u32(const void* p) {
    uint32_t a;
    asm("{ .reg .u64 t; cvta.to.shared.u64 t, %1; cvt.u32.u64 %0, t; }"
        : "=r"(a) : "l"(p));
    return a;
}

__device__ __forceinline__ void mbar_wait(uint32_t mbar_a, uint32_t parity) {
    uint32_t done;
    asm volatile(
        "{\n\t.reg .pred p;\n\t"
        "mbarrier.try_wait.parity.acquire.cta.shared::cta.b64 p, [%1], %2;\n\t"
        "selp.b32 %0, 1, 0, p;\n\t}"
        : "=r"(done) : "r"(mbar_a), "r"(parity) : "memory");
    if (!done) {
        asm volatile(
            "{\n\t.reg .pred P1;\n\t"
            "WL_%=:\n\t"
            "mbarrier.try_wait.parity.acquire.cta.shared::cta.b64 P1, [%0], %1, 0x989680;\n\t"
            "@P1 bra.uni WD_%=;\n\t"
            "bra.uni WL_%=;\n\t"
            "WD_%=:\n\t}"
            :: "r"(mbar_a), "r"(parity) : "memory");
    }
}

__global__ void __launch_bounds__(THREADS, 2)
disturbance_loss_fused(const float* __restrict__ out, float* __restrict__ d_out) {
    extern __shared__ char smem_raw[];
    uint64_t* mbar = (uint64_t*)smem_raw;            // STAGES barriers
    float*    rows = (float*)(smem_raw + 1024);      // STAGES x 16 KB row buffers

    const uint32_t mbar_a = smem_u32(mbar);
    const uint32_t rows_a = smem_u32(rows);
    const int t = threadIdx.x;

    // This block's 4096-px span: contiguous in hw within one batch image b.
    const int p0 = blockIdx.x * SPAN;
    const int b  = p0 >> 16;                          // SPAN divides HW_, so one b per block
    const int hw = p0 & (HW_ - 1);
    const float* __restrict__ gbase = out + (size_t)b * (Y_ * HW_) + hw;

    if (t == 0) {
#pragma unroll
        for (int s = 0; s < STAGES; ++s)
            asm volatile("mbarrier.init.shared.b64 [%0], 1;"
                         :: "r"(mbar_a + s * 8) : "memory");
    }
    __syncthreads();

    // Issue one 16 KB contiguous row copy into stage s.
    auto issue_row = [&](int y, int s) {
        asm volatile("mbarrier.arrive.expect_tx.shared.b64 _, [%0], %1;"
                     :: "r"(mbar_a + s * 8), "r"((uint32_t)ROW_BYTES) : "memory");
        asm volatile(
            "cp.async.bulk.shared::cta.global.mbarrier::complete_tx::bytes "
            "[%0], [%1], %2, [%3];"
            :: "r"(rows_a + s * ROW_BYTES),
               "l"(gbase + (size_t)y * HW_),
               "r"((uint32_t)ROW_BYTES),
               "r"(mbar_a + s * 8)
            : "memory");
    };

    if (t == 0) {
#pragma unroll
        for (int s = 0; s < STAGES; ++s) issue_row(s, s);
    }

    // Per-pixel streaming state (8 px/thread, contiguous: px = t*8 + k).
    float T0[PPT], T1[PPT], T2[PPT], prev[PPT], dmin[PPT];
#pragma unroll
    for (int k = 0; k < PPT; ++k) {
        T0[k] = T1[k] = T2[k] = 0.f; prev[k] = 0.f; dmin[k] = 0.f;
    }

#pragma unroll
    for (int y = 0; y < Y_; ++y) {
        const int s = y % STAGES;
        mbar_wait(mbar_a + s * 8, (uint32_t)((y / STAGES) & 1));

        const float4* rp = (const float4*)(rows + s * SPAN) + t * 2;
        float4 u0 = rp[0], u1 = rp[1];
        float u[PPT] = {u0.x, u0.y, u0.z, u0.w, u1.x, u1.y, u1.z, u1.w};

        const float yf = (float)y;
#pragma unroll
        for (int k = 0; k < PPT; ++k) {
            if (y >= 2 && y <= Y_ - 2)
                dmin[k] = fminf(dmin[k], u[k] - prev[k]);
            T0[k] += u[k];
            T1[k] = fmaf(yf, u[k], T1[k]);
            T2[k] = fmaf(u[k], u[k], T2[k]);
            prev[k] = u[k];
        }

        __syncthreads();                       // all readers done with stage s
        if (t == 0 && y + STAGES < Y_) issue_row(y + STAGES, s);
    }

    // Any pixel in this warp needing the exact-argmin slow path? (~4e-7/elem)
    float dm = dmin[0];
#pragma unroll
    for (int k = 1; k < PPT; ++k) dm = fminf(dm, dmin[k]);
    const bool any_slow = __ballot_sync(0xFFFFFFFFu, dm < -DIST_IND) != 0u;

    float contrib = 0.f;
#pragma unroll
    for (int k = 0; k < PPT; ++k) {
        int   f = 0;
        float s0 = 0.f, s1 = 0.f, s2 = 0.f;

        if (any_slow && dmin[k] < -DIST_IND) {
            // Rare: exact first-occurrence argmin with prefix snapshots,
            // re-reading this pixel's column from global (L2-hot).
            const float* pb = gbase + t * PPT + k;
            float best = -DIST_IND;
            float q0 = 0.f, q1 = 0.f, q2 = 0.f, pv = 0.f;
#pragma unroll 1
            for (int y = 0; y < Y_; ++y) {
                float uu = __ldg(pb + (size_t)y * HW_);
                if (y >= 2 && y <= Y_ - 2) {
                    float d = uu - pv;
                    if (d < best) { best = d; f = y; s0 = q0; s1 = q1; s2 = q2; }
                }
                q0 += uu;
                q1 = fmaf((float)y, uu, q1);
                q2 = fmaf(uu, uu, q2);
                pv = uu;
            }
        }

        const float ff = (float)f;
        const int   m  = Y_ - f;

        const float n_b   = ff;
        const float sx_b  = (float)(f * (f - 1) / 2);
        const float sxx_b = (float)((f - 1) * f * (2 * f - 1) / 6);
        const float sy_b  = s0, sxy_b = s1, syy_b = s2;

        const float n_a   = (float)m;
        const float sx_a  = (float)(m * (m - 1) / 2);
        const float sxx_a = (float)((m - 1) * m * (2 * m - 1) / 6);
        const float sy_a  = T0[k] - s0;
        const float sxy_a = (T1[k] - s1) - ff * sy_a;
        const float syy_a = T2[k] - s2;

        {   // before
            float ns  = fmaxf(n_b, 1.0f);
            float cov = sxy_b - sx_b * sy_b / ns;
            float var = sxx_b - sx_b * sx_b / ns;
            float vs  = (var > 0.f) ? var : 1.f;
            float sl  = fminf(fmaxf(cov / vs, 0.f), 2.f);
            float c   = (sy_b - sl * sx_b) / ns;
            float res = syy_b - 2.f * sl * sxy_b - 2.f * c * sy_b
                      + sl * sl * sxx_b + 2.f * sl * c * sx_b + c * c * n_b;
            if (n_b >= 3.f) contrib += res;
        }
        {   // after
            float ns  = fmaxf(n_a, 1.0f);
            float cov = sxy_a - sx_a * sy_a / ns;
            float var = sxx_a - sx_a * sx_a / ns;
            float vs  = (var > 0.f) ? var : 1.f;
            float sl  = fminf(fmaxf(cov / vs, 0.f), 2.f);
            float c   = (sy_a - sl * sx_a) / ns;
            float res = syy_a - 2.f * sl * sxy_a - 2.f * c * sy_a
                      + sl * sl * sxx_a + 2.f * sl * c * sx_a + c * c * n_a;
            if (n_a >= 3.f) contrib += res;
        }
    }

    // ---- deterministic in-block reduction ----
    const unsigned lane = threadIdx.x & 31u;
    const unsigned wid  = threadIdx.x >> 5;
    float w = contrib;
#pragma unroll
    for (int o = 16; o > 0; o >>= 1)
        w += __shfl_down_sync(0xFFFFFFFFu, w, o);

    __shared__ float warpsum[THREADS / 32];
    if (lane == 0) warpsum[wid] = w;
    __syncthreads();

    __shared__ bool is_last;
    if (wid == 0) {
        float x = (lane < THREADS / 32) ? warpsum[lane] : 0.f;
#pragma unroll
        for (int o = 8; o > 0; o >>= 1)
            x += __shfl_down_sync(0xFFFFFFFFu, x, o);
        if (lane == 0) {
            g_partials[blockIdx.x] = (double)x;
            __threadfence();
            unsigned done = atomicAdd(&g_count, 1u);
            is_last = (done == (unsigned)(GRID - 1));
        }
    }
    __syncthreads();

    // ---- last block sums all partials in fixed index order (deterministic) ----
    if (is_last) {
        __threadfence();
        double sd = 0.0;
        for (int i = threadIdx.x; i < GRID; i += THREADS)
            sd += g_partials[i];
#pragma unroll
        for (int o = 16; o > 0; o >>= 1)
            sd += __shfl_down_sync(0xFFFFFFFFu, sd, o);
        __shared__ double wsum[THREADS / 32];
        if (lane == 0) wsum[wid] = sd;
        __syncthreads();
        if (wid == 0) {
            double uu = (lane < THREADS / 32) ? wsum[lane] : 0.0;
#pragma unroll
            for (int o = 8; o > 0; o >>= 1)
                uu += __shfl_down_sync(0xFFFFFFFFu, uu, o);
            if (lane == 0) {
                d_out[0] = (float)(uu / ((double)Y_ * (double)NPIX));
                g_count = 0;   // reset for next graph replay
            }
        }
    }
}

extern "C" void kernel_launch(void* const* d_in, const int* in_sizes, int n_in,
                              void* d_out, int out_size) {
    const float* out = (const float*)d_in[0];   // 'target' (d_in[1]) unused by reference
    (void)in_sizes; (void)n_in; (void)out_size;

    static bool configured = false;
    if (!configured) {
        cudaFuncSetAttribute(disturbance_loss_fused,
                             cudaFuncAttributeMaxDynamicSharedMemorySize, SMEM_BYTES);
        configured = true;
    }
    disturbance_loss_fused<<<GRID, THREADS, SMEM_BYTES>>>(out, (float*)d_out);
}

// round 10
// speedup vs baseline: 1.2463x; 1.2463x over previous
#include <cuda_runtime.h>

// Problem shape (fixed by reference setup_inputs)
#define B_   16
#define Y_   32
#define HW_  65536                 // H*W = 256*256
#define NPIX (B_ * HW_)            // 1048576
#define THREADS 256
#define PPT 2                      // pixels per thread (float2 loads)
#define NBLOCKS (NPIX / (THREADS * PPT))  // 2048
#define CHUNK 8                    // rows front-batched per buffer
#define DIST_IND 7.0f

__device__ double g_partials[NBLOCKS];
__device__ unsigned int g_count = 0;

// Cheap streaming update for one 8-row chunk (dmin-only argmin tracking).
#define PROCESS_CHUNK(Y0, BUF)                                               \
    do {                                                                     \
        _Pragma("unroll")                                                    \
        for (int i = 0; i < CHUNK; ++i) {                                    \
            const int   y  = (Y0) + i;                                       \
            const float yf = (float)y;                                       \
            float u0 = (BUF)[i].x, u1 = (BUF)[i].y;                          \
            if (y >= 2 && y <= Y_ - 2) {                                     \
                dmin0 = fminf(dmin0, u0 - prev0);                            \
                dmin1 = fminf(dmin1, u1 - prev1);                            \
            }                                                                \
            A0 += u0;                     B0 += u1;                          \
            A1 = fmaf(yf, u0, A1);        B1 = fmaf(yf, u1, B1);             \
            A2 = fmaf(u0, u0, A2);        B2 = fmaf(u1, u1, B2);             \
            prev0 = u0;                   prev1 = u1;                        \
        }                                                                    \
    } while (0)

__global__ void __launch_bounds__(THREADS, 6)
disturbance_loss_fused(const float* __restrict__ out, float* __restrict__ d_out) {
    const int gt = blockIdx.x * THREADS + threadIdx.x;
    const int p2 = gt * PPT;                 // first of 2 adjacent pixels
    const int b  = p2 >> 16;
    const int hw = p2 & (HW_ - 1);
    const float2* __restrict__ base =
        (const float2*)(out + (size_t)b * (Y_ * HW_) + hw);
    const int rs = HW_ / 2;                  // row stride in float2

    float A0 = 0.f, A1 = 0.f, A2 = 0.f;      // pixel 0 running sums: v, y*v, v*v
    float B0 = 0.f, B1 = 0.f, B2 = 0.f;      // pixel 1
    float dmin0 = 0.f, dmin1 = 0.f, prev0 = 0.f, prev1 = 0.f;

    // R3's winning load structure: two 8-deep float2 buffers, software pipelined.
    float2 b0[CHUNK], b1[CHUNK];
#pragma unroll
    for (int i = 0; i < CHUNK; ++i) b0[i] = __ldg(&base[i * rs]);
#pragma unroll
    for (int i = 0; i < CHUNK; ++i) b1[i] = __ldg(&base[(CHUNK + i) * rs]);

    PROCESS_CHUNK(0, b0);
#pragma unroll
    for (int i = 0; i < CHUNK; ++i) b0[i] = __ldg(&base[(2 * CHUNK + i) * rs]);
    PROCESS_CHUNK(CHUNK, b1);
#pragma unroll
    for (int i = 0; i < CHUNK; ++i) b1[i] = __ldg(&base[(3 * CHUNK + i) * rs]);
    PROCESS_CHUNK(2 * CHUNK, b0);
    PROCESS_CHUNK(3 * CHUNK, b1);

    // Rare slow path (~4e-7/elem): exact first-occurrence argmin w/ snapshots.
    int   f0 = 0, f1 = 0;
    float s00 = 0.f, s01 = 0.f, s02 = 0.f;
    float s10 = 0.f, s11 = 0.f, s12 = 0.f;
    if (__ballot_sync(0xFFFFFFFFu, fminf(dmin0, dmin1) < -DIST_IND)) {
        const float* pb = (const float*)base;
#pragma unroll 1
        for (int px = 0; px < PPT; ++px) {
            float best = -DIST_IND;
            float q0 = 0.f, q1 = 0.f, q2 = 0.f, pv = 0.f;
            int   fx = 0;
            float t0 = 0.f, t1 = 0.f, t2 = 0.f;
#pragma unroll 1
            for (int y = 0; y < Y_; ++y) {
                float u = __ldg(pb + px + (size_t)y * HW_);   // L2-hot
                if (y >= 2 && y <= Y_ - 2) {
                    float d = u - pv;
                    if (d < best) { best = d; fx = y; t0 = q0; t1 = q1; t2 = q2; }
                }
                q0 += u;
                q1 = fmaf((float)y, u, q1);
                q2 = fmaf(u, u, q2);
                pv = u;
            }
            if (px == 0) { f0 = fx; s00 = t0; s01 = t1; s02 = t2; }
            else         { f1 = fx; s10 = t0; s11 = t1; s12 = t2; }
        }
    }

    // Closed-form regression + residuals for both pixels.
    float contrib = 0.f;
#pragma unroll
    for (int px = 0; px < PPT; ++px) {
        const int   f  = (px == 0) ? f0 : f1;
        const float T0 = (px == 0) ? A0 : B0;
        const float T1 = (px == 0) ? A1 : B1;
        const float T2 = (px == 0) ? A2 : B2;
        const float s0 = (px == 0) ? s00 : s10;
        const float s1 = (px == 0) ? s01 : s11;
        const float s2 = (px == 0) ? s02 : s12;

        const float ff = (float)f;
        const int   m  = Y_ - f;

        const float n_b   = ff;
        const float sx_b  = (float)(f * (f - 1) / 2);
        const float sxx_b = (float)((f - 1) * f * (2 * f - 1) / 6);

        const float n_a   = (float)m;
        const float sx_a  = (float)(m * (m - 1) / 2);
        const float sxx_a = (float)((m - 1) * m * (2 * m - 1) / 6);
        const float sy_a  = T0 - s0;
        const float sxy_a = (T1 - s1) - ff * sy_a;
        const float syy_a = T2 - s2;

        {   // before
            float ns  = fmaxf(n_b, 1.0f);
            float cov = s1 - sx_b * s0 / ns;
            float var = sxx_b - sx_b * sx_b / ns;
            float vs  = (var > 0.f) ? var : 1.f;
            float sl  = fminf(fmaxf(cov / vs, 0.f), 2.f);
            float c   = (s0 - sl * sx_b) / ns;
            float res = s2 - 2.f * sl * s1 - 2.f * c * s0
                      + sl * sl * sxx_b + 2.f * sl * c * sx_b + c * c * n_b;
            if (n_b >= 3.f) contrib += res;
        }
        {   // after
            float ns  = fmaxf(n_a, 1.0f);
            float cov = sxy_a - sx_a * sy_a / ns;
            float var = sxx_a - sx_a * sx_a / ns;
            float vs  = (var > 0.f) ? var : 1.f;
            float sl  = fminf(fmaxf(cov / vs, 0.f), 2.f);
            float c   = (sy_a - sl * sx_a) / ns;
            float res = syy_a - 2.f * sl * sxy_a - 2.f * c * sy_a
                      + sl * sl * sxx_a + 2.f * sl * c * sx_a + c * c * n_a;
            if (n_a >= 3.f) contrib += res;
        }
    }

    // ---- deterministic in-block reduction ----
    const unsigned lane = threadIdx.x & 31u;
    const unsigned wid  = threadIdx.x >> 5;
    float w = contrib;
#pragma unroll
    for (int o = 16; o > 0; o >>= 1)
        w += __shfl_down_sync(0xFFFFFFFFu, w, o);

    __shared__ float warpsum[THREADS / 32];
    if (lane == 0) warpsum[wid] = w;
    __syncthreads();

    __shared__ bool is_last;
    if (wid == 0) {
        float x = (lane < THREADS / 32) ? warpsum[lane] : 0.f;
#pragma unroll
        for (int o = 4; o > 0; o >>= 1)
            x += __shfl_down_sync(0xFFFFFFFFu, x, o);
        if (lane == 0) {
            g_partials[blockIdx.x] = (double)x;
            __threadfence();
            unsigned done = atomicAdd(&g_count, 1u);
            is_last = (done == (unsigned)(NBLOCKS - 1));
        }
    }
    __syncthreads();

    // ---- last block sums all partials in fixed index order (deterministic) ----
    if (is_last) {
        __threadfence();
        double sd = 0.0;
#pragma unroll
        for (int k = 0; k < NBLOCKS / THREADS; ++k)
            sd += g_partials[threadIdx.x + k * THREADS];
#pragma unroll
        for (int o = 16; o > 0; o >>= 1)
            sd += __shfl_down_sync(0xFFFFFFFFu, sd, o);
        __shared__ double wsum[THREADS / 32];
        if (lane == 0) wsum[wid] = sd;
        __syncthreads();
        if (wid == 0) {
            double u = (lane < THREADS / 32) ? wsum[lane] : 0.0;
#pragma unroll
            for (int o = 4; o > 0; o >>= 1)
                u += __shfl_down_sync(0xFFFFFFFFu, u, o);
            if (lane == 0) {
                d_out[0] = (float)(u / ((double)Y_ * (double)NPIX));
                g_count = 0;   // reset for next graph replay
            }
        }
    }
}

extern "C" void kernel_launch(void* const* d_in, const int* in_sizes, int n_in,
                              void* d_out, int out_size) {
    const float* out = (const float*)d_in[0];   // 'target' (d_in[1]) unused by reference
    (void)in_sizes; (void)n_in; (void)out_size;
    disturbance_loss_fused<<<NBLOCKS, THREADS>>>(out, (float*)d_out);
}

// round 11
// speedup vs baseline: 1.3928x; 1.1175x over previous
#include <cuda_runtime.h>

// Problem shape (fixed by reference setup_inputs)
#define B_   16
#define Y_   32
#define HW_  65536                 // H*W = 256*256
#define NPIX (B_ * HW_)            // 1048576
#define THREADS 256
#define PPT 2                      // pixels per thread (float2 loads)
#define NBLOCKS (NPIX / (THREADS * PPT))  // 2048
#define CHUNK 8                    // rows front-batched per buffer
#define DIST_IND 7.0f

__device__ double g_partials[NBLOCKS];
__device__ unsigned int g_count = 0;

// Per-segment-length tables (n in [0,32]):
//   c_sx[n]   = n(n-1)/2
//   c_sxx[n]  = (n-1)n(2n-1)/6
//   c_invn[n] = 1/max(n,1)
//   c_invv[n] = 1/var_safe,  var = sxx - sx^2/max(n,1)
__constant__ float c_sx[33] = {
    0,0,1,3,6,10,15,21,28,36,45,55,66,78,91,105,120,136,153,171,190,210,231,
    253,276,300,325,351,378,406,435,465,496
};
__constant__ float c_sxx[33] = {
    0,0,1,5,14,30,55,91,140,204,285,385,506,650,819,1015,1240,1496,1785,2109,
    2470,2870,3311,3795,4324,4900,5525,6201,6930,7714,8555,9455,10416
};
__constant__ float c_invn[33] = {
    1.f, 1.f, 0.5f, 1.f/3, 0.25f, 0.2f, 1.f/6, 1.f/7, 0.125f, 1.f/9, 0.1f,
    1.f/11, 1.f/12, 1.f/13, 1.f/14, 1.f/15, 0.0625f, 1.f/17, 1.f/18, 1.f/19,
    0.05f, 1.f/21, 1.f/22, 1.f/23, 1.f/24, 0.04f, 1.f/26, 1.f/27, 1.f/28,
    1.f/29, 1.f/30, 1.f/31, 0.03125f
};
// var[n] = sxx[n] - sx[n]^2/n  (n>=2): n(n-1)(n+1)/12
__constant__ float c_invv[33] = {
    1.f, 1.f, 1.f/0.5f, 1.f/2.f, 1.f/5.f, 1.f/10.f, 1.f/17.5f, 1.f/28.f,
    1.f/42.f, 1.f/60.f, 1.f/82.5f, 1.f/110.f, 1.f/143.f, 1.f/182.f, 1.f/227.5f,
    1.f/280.f, 1.f/340.f, 1.f/408.f, 1.f/484.5f, 1.f/570.f, 1.f/665.f,
    1.f/770.f, 1.f/885.5f, 1.f/1012.f, 1.f/1150.f, 1.f/1300.f, 1.f/1462.5f,
    1.f/1638.f, 1.f/1827.f, 1.f/2030.f, 1.f/2247.5f, 1.f/2480.f, 1.f/2728.f
};

// Cheap streaming update for one 8-row chunk (dmin-only argmin tracking).
#define PROCESS_CHUNK(Y0, BUF)                                               \
    do {                                                                     \
        _Pragma("unroll")                                                    \
        for (int i = 0; i < CHUNK; ++i) {                                    \
            const int   y  = (Y0) + i;                                       \
            const float yf = (float)y;                                       \
            float u0 = (BUF)[i].x, u1 = (BUF)[i].y;                          \
            if (y >= 2 && y <= Y_ - 2) {                                     \
                dmin0 = fminf(dmin0, u0 - prev0);                            \
                dmin1 = fminf(dmin1, u1 - prev1);                            \
            }                                                                \
            A0 += u0;                     B0 += u1;                          \
            A1 = fmaf(yf, u0, A1);        B1 = fmaf(yf, u1, B1);             \
            A2 = fmaf(u0, u0, A2);        B2 = fmaf(u1, u1, B2);             \
            prev0 = u0;                   prev1 = u1;                        \
        }                                                                    \
    } while (0)

// Table-driven regression+residual: no divisions.
__device__ __forceinline__ float seg_res(int n, float sy, float sxy, float syy) {
    const float sx   = c_sx[n];
    const float sxx  = c_sxx[n];
    const float invn = c_invn[n];
    const float invv = c_invv[n];
    float cov = sxy - sx * sy * invn;
    float sl  = fminf(fmaxf(cov * invv, 0.f), 2.f);
    float c   = (sy - sl * sx) * invn;
    float res = syy - 2.f * sl * sxy - 2.f * c * sy
              + sl * sl * sxx + 2.f * sl * c * sx + c * c * (float)n;
    return (n >= 3) ? res : 0.f;
}

__global__ void __launch_bounds__(THREADS, 4)
disturbance_loss_fused(const float* __restrict__ out, float* __restrict__ d_out) {
    const int gt = blockIdx.x * THREADS + threadIdx.x;
    const int p2 = gt * PPT;                 // first of 2 adjacent pixels
    const int b  = p2 >> 16;
    const int hw = p2 & (HW_ - 1);
    const float2* __restrict__ base =
        (const float2*)(out + (size_t)b * (Y_ * HW_) + hw);
    const int rs = HW_ / 2;                  // row stride in float2

    float A0 = 0.f, A1 = 0.f, A2 = 0.f;      // pixel 0 running sums: v, y*v, v*v
    float B0 = 0.f, B1 = 0.f, B2 = 0.f;      // pixel 1
    float dmin0 = 0.f, dmin1 = 0.f, prev0 = 0.f, prev1 = 0.f;

    // R3's winning load structure: two 8-deep float2 buffers, software pipelined.
    float2 b0[CHUNK], b1[CHUNK];
#pragma unroll
    for (int i = 0; i < CHUNK; ++i) b0[i] = __ldg(&base[i * rs]);
#pragma unroll
    for (int i = 0; i < CHUNK; ++i) b1[i] = __ldg(&base[(CHUNK + i) * rs]);

    PROCESS_CHUNK(0, b0);
#pragma unroll
    for (int i = 0; i < CHUNK; ++i) b0[i] = __ldg(&base[(2 * CHUNK + i) * rs]);
    PROCESS_CHUNK(CHUNK, b1);
#pragma unroll
    for (int i = 0; i < CHUNK; ++i) b1[i] = __ldg(&base[(3 * CHUNK + i) * rs]);
    PROCESS_CHUNK(2 * CHUNK, b0);
    PROCESS_CHUNK(3 * CHUNK, b1);

    // Rare slow path (~4e-7/elem): exact first-occurrence argmin w/ snapshots.
    int   f0 = 0, f1 = 0;
    float s00 = 0.f, s01 = 0.f, s02 = 0.f;
    float s10 = 0.f, s11 = 0.f, s12 = 0.f;
    if (__ballot_sync(0xFFFFFFFFu, fminf(dmin0, dmin1) < -DIST_IND)) {
        const float* pb = (const float*)base;
#pragma unroll 1
        for (int px = 0; px < PPT; ++px) {
            float best = -DIST_IND;
            float q0 = 0.f, q1 = 0.f, q2 = 0.f, pv = 0.f;
            int   fx = 0;
            float t0 = 0.f, t1 = 0.f, t2 = 0.f;
#pragma unroll 1
            for (int y = 0; y < Y_; ++y) {
                float u = __ldg(pb + px + (size_t)y * HW_);   // L2-hot
                if (y >= 2 && y <= Y_ - 2) {
                    float d = u - pv;
                    if (d < best) { best = d; fx = y; t0 = q0; t1 = q1; t2 = q2; }
                }
                q0 += u;
                q1 = fmaf((float)y, u, q1);
                q2 = fmaf(u, u, q2);
                pv = u;
            }
            if (px == 0) { f0 = fx; s00 = t0; s01 = t1; s02 = t2; }
            else         { f1 = fx; s10 = t0; s11 = t1; s12 = t2; }
        }
    }

    // Closed-form regression + residuals (table-driven, division-free).
    float contrib;
    {
        const float ff0 = (float)f0;
        const float sy_a0  = A0 - s00;
        const float sxy_a0 = (A1 - s01) - ff0 * sy_a0;
        const float syy_a0 = A2 - s02;
        contrib  = seg_res(f0, s00, s01, s02);
        contrib += seg_res(Y_ - f0, sy_a0, sxy_a0, syy_a0);

        const float ff1 = (float)f1;
        const float sy_a1  = B0 - s10;
        const float sxy_a1 = (B1 - s11) - ff1 * sy_a1;
        const float syy_a1 = B2 - s12;
        contrib += seg_res(f1, s10, s11, s12);
        contrib += seg_res(Y_ - f1, sy_a1, sxy_a1, syy_a1);
    }

    // ---- deterministic in-block reduction ----
    const unsigned lane = threadIdx.x & 31u;
    const unsigned wid  = threadIdx.x >> 5;
    float w = contrib;
#pragma unroll
    for (int o = 16; o > 0; o >>= 1)
        w += __shfl_down_sync(0xFFFFFFFFu, w, o);

    __shared__ float warpsum[THREADS / 32];
    if (lane == 0) warpsum[wid] = w;
    __syncthreads();

    __shared__ bool is_last;
    if (wid == 0) {
        float x = (lane < THREADS / 32) ? warpsum[lane] : 0.f;
#pragma unroll
        for (int o = 4; o > 0; o >>= 1)
            x += __shfl_down_sync(0xFFFFFFFFu, x, o);
        if (lane == 0) {
            g_partials[blockIdx.x] = (double)x;
            __threadfence();
            unsigned done = atomicAdd(&g_count, 1u);
            is_last = (done == (unsigned)(NBLOCKS - 1));
        }
    }
    __syncthreads();

    // ---- last block sums all partials in fixed index order (deterministic) ----
    if (is_last) {
        __threadfence();
        double sd = 0.0;
#pragma unroll
        for (int k = 0; k < NBLOCKS / THREADS; ++k)
            sd += g_partials[threadIdx.x + k * THREADS];
#pragma unroll
        for (int o = 16; o > 0; o >>= 1)
            sd += __shfl_down_sync(0xFFFFFFFFu, sd, o);
        __shared__ double wsum[THREADS / 32];
        if (lane == 0) wsum[wid] = sd;
        __syncthreads();
        if (wid == 0) {
            double u = (lane < THREADS / 32) ? wsum[lane] : 0.0;
#pragma unroll
            for (int o = 4; o > 0; o >>= 1)
                u += __shfl_down_sync(0xFFFFFFFFu, u, o);
            if (lane == 0) {
                d_out[0] = (float)(u / ((double)Y_ * (double)NPIX));
                g_count = 0;   // reset for next graph replay
            }
        }
    }
}

extern "C" void kernel_launch(void* const* d_in, const int* in_sizes, int n_in,
                              void* d_out, int out_size) {
    const float* out = (const float*)d_in[0];   // 'target' (d_in[1]) unused by reference
    (void)in_sizes; (void)n_in; (void)out_size;
    disturbance_loss_fused<<<NBLOCKS, THREADS>>>(out, (float*)d_out);
}

// round 12
// speedup vs baseline: 1.4090x; 1.0116x over previous
#include <cuda_runtime.h>

// Problem shape (fixed by reference setup_inputs)
#define B_   16
#define Y_   32
#define HW_  65536                 // H*W = 256*256
#define NPIX (B_ * HW_)            // 1048576
#define THREADS 256
#define PPT 4                      // pixels per thread (float4 loads)
#define NBLOCKS (NPIX / (THREADS * PPT))  // 1024
#define CHUNK 4                    // rows front-batched per buffer
#define DIST_IND 7.0f

__device__ double g_partials[NBLOCKS];
__device__ unsigned int g_count = 0;

// Per-segment-length tables (n in [0,32]).
__constant__ float c_sx[33] = {
    0,0,1,3,6,10,15,21,28,36,45,55,66,78,91,105,120,136,153,171,190,210,231,
    253,276,300,325,351,378,406,435,465,496
};
__constant__ float c_sxx[33] = {
    0,0,1,5,14,30,55,91,140,204,285,385,506,650,819,1015,1240,1496,1785,2109,
    2470,2870,3311,3795,4324,4900,5525,6201,6930,7714,8555,9455,10416
};
__constant__ float c_invn[33] = {
    1.f, 1.f, 0.5f, 1.f/3, 0.25f, 0.2f, 1.f/6, 1.f/7, 0.125f, 1.f/9, 0.1f,
    1.f/11, 1.f/12, 1.f/13, 1.f/14, 1.f/15, 0.0625f, 1.f/17, 1.f/18, 1.f/19,
    0.05f, 1.f/21, 1.f/22, 1.f/23, 1.f/24, 0.04f, 1.f/26, 1.f/27, 1.f/28,
    1.f/29, 1.f/30, 1.f/31, 0.03125f
};
// var[n] = n(n-1)(n+1)/12 for n>=2; var_safe=1 for n<2.
__constant__ float c_invv[33] = {
    1.f, 1.f, 1.f/0.5f, 1.f/2.f, 1.f/5.f, 1.f/10.f, 1.f/17.5f, 1.f/28.f,
    1.f/42.f, 1.f/60.f, 1.f/82.5f, 1.f/110.f, 1.f/143.f, 1.f/182.f, 1.f/227.5f,
    1.f/280.f, 1.f/340.f, 1.f/408.f, 1.f/484.5f, 1.f/570.f, 1.f/665.f,
    1.f/770.f, 1.f/885.5f, 1.f/1012.f, 1.f/1150.f, 1.f/1300.f, 1.f/1462.5f,
    1.f/1638.f, 1.f/1827.f, 1.f/2030.f, 1.f/2247.5f, 1.f/2480.f, 1.f/2728.f
};

__device__ __forceinline__ float seg_res(int n, float sy, float sxy, float syy) {
    const float sx   = c_sx[n];
    const float sxx  = c_sxx[n];
    const float invn = c_invn[n];
    const float invv = c_invv[n];
    float cov = sxy - sx * sy * invn;
    float sl  = fminf(fmaxf(cov * invv, 0.f), 2.f);
    float c   = (sy - sl * sx) * invn;
    float res = syy - 2.f * sl * sxy - 2.f * c * sy
              + sl * sl * sxx + 2.f * sl * c * sx + c * c * (float)n;
    return (n >= 3) ? res : 0.f;
}

// Process one 4-row float4 chunk: cheap streaming update, per-pixel dmin.
#define PROCESS_CHUNK(Y0, BUF)                                                \
    do {                                                                      \
        _Pragma("unroll")                                                     \
        for (int i = 0; i < CHUNK; ++i) {                                     \
            const int   y  = (Y0) + i;                                        \
            const float yf = (float)y;                                        \
            float u[PPT] = {(BUF)[i].x, (BUF)[i].y, (BUF)[i].z, (BUF)[i].w};  \
            _Pragma("unroll")                                                 \
            for (int k = 0; k < PPT; ++k) {                                   \
                if (y >= 2 && y <= Y_ - 2)                                    \
                    dmin[k] = fminf(dmin[k], u[k] - prev[k]);                 \
                A0[k] += u[k];                                                \
                A1[k] = fmaf(yf, u[k], A1[k]);                                \
                A2[k] = fmaf(u[k], u[k], A2[k]);                              \
                prev[k] = u[k];                                               \
            }                                                                 \
        }                                                                     \
    } while (0)

__global__ void __launch_bounds__(THREADS, 4)
disturbance_loss_fused(const float* __restrict__ out, float* __restrict__ d_out) {
    const int gt = blockIdx.x * THREADS + threadIdx.x;
    const int p4 = gt * PPT;                 // first of 4 adjacent pixels
    const int b  = p4 >> 16;
    const int hw = p4 & (HW_ - 1);
    const float4* __restrict__ base =
        (const float4*)(out + (size_t)b * (Y_ * HW_) + hw);
    const int rs = HW_ / 4;                  // row stride in float4 (16384)

    float A0[PPT], A1[PPT], A2[PPT], prev[PPT], dmin[PPT];
#pragma unroll
    for (int k = 0; k < PPT; ++k) {
        A0[k] = A1[k] = A2[k] = 0.f; prev[k] = 0.f; dmin[k] = 0.f;
    }

    // Double-buffered float4 pipeline: 4 LDG.128 in flight per buffer.
    float4 b0[CHUNK], b1[CHUNK];
#pragma unroll
    for (int i = 0; i < CHUNK; ++i) b0[i] = __ldg(&base[i * rs]);
#pragma unroll
    for (int i = 0; i < CHUNK; ++i) b1[i] = __ldg(&base[(CHUNK + i) * rs]);

    PROCESS_CHUNK(0, b0);
#pragma unroll
    for (int i = 0; i < CHUNK; ++i) b0[i] = __ldg(&base[(2 * CHUNK + i) * rs]);
    PROCESS_CHUNK(1 * CHUNK, b1);
#pragma unroll
    for (int i = 0; i < CHUNK; ++i) b1[i] = __ldg(&base[(3 * CHUNK + i) * rs]);
    PROCESS_CHUNK(2 * CHUNK, b0);
#pragma unroll
    for (int i = 0; i < CHUNK; ++i) b0[i] = __ldg(&base[(4 * CHUNK + i) * rs]);
    PROCESS_CHUNK(3 * CHUNK, b1);
#pragma unroll
    for (int i = 0; i < CHUNK; ++i) b1[i] = __ldg(&base[(5 * CHUNK + i) * rs]);
    PROCESS_CHUNK(4 * CHUNK, b0);
#pragma unroll
    for (int i = 0; i < CHUNK; ++i) b0[i] = __ldg(&base[(6 * CHUNK + i) * rs]);
    PROCESS_CHUNK(5 * CHUNK, b1);
#pragma unroll
    for (int i = 0; i < CHUNK; ++i) b1[i] = __ldg(&base[(7 * CHUNK + i) * rs]);
    PROCESS_CHUNK(6 * CHUNK, b0);
    PROCESS_CHUNK(7 * CHUNK, b1);

    // Rare slow path (~4e-7/elem): exact first-occurrence argmin w/ snapshots.
    int   f[PPT]  = {0, 0, 0, 0};
    float s0[PPT] = {0.f, 0.f, 0.f, 0.f};
    float s1[PPT] = {0.f, 0.f, 0.f, 0.f};
    float s2[PPT] = {0.f, 0.f, 0.f, 0.f};
    float dm = fminf(fminf(dmin[0], dmin[1]), fminf(dmin[2], dmin[3]));
    if (__ballot_sync(0xFFFFFFFFu, dm < -DIST_IND)) {
        const float* pb = (const float*)base;
#pragma unroll 1
        for (int px = 0; px < PPT; ++px) {
            if (dmin[px] < -DIST_IND) {
                float best = -DIST_IND;
                float q0 = 0.f, q1 = 0.f, q2 = 0.f, pv = 0.f;
#pragma unroll 1
                for (int y = 0; y < Y_; ++y) {
                    float u = __ldg(pb + px + (size_t)y * HW_);   // L2-hot
                    if (y >= 2 && y <= Y_ - 2) {
                        float d = u - pv;
                        if (d < best) {
                            best = d; f[px] = y;
                            s0[px] = q0; s1[px] = q1; s2[px] = q2;
                        }
                    }
                    q0 += u;
                    q1 = fmaf((float)y, u, q1);
                    q2 = fmaf(u, u, q2);
                    pv = u;
                }
            }
        }
    }

    // Closed-form regression + residuals (table-driven, division-free).
    float contrib = 0.f;
#pragma unroll
    for (int k = 0; k < PPT; ++k) {
        const float ff    = (float)f[k];
        const float sy_a  = A0[k] - s0[k];
        const float sxy_a = (A1[k] - s1[k]) - ff * sy_a;
        const float syy_a = A2[k] - s2[k];
        contrib += seg_res(f[k], s0[k], s1[k], s2[k]);
        contrib += seg_res(Y_ - f[k], sy_a, sxy_a, syy_a);
    }

    // ---- deterministic in-block reduction ----
    const unsigned lane = threadIdx.x & 31u;
    const unsigned wid  = threadIdx.x >> 5;
    float w = contrib;
#pragma unroll
    for (int o = 16; o > 0; o >>= 1)
        w += __shfl_down_sync(0xFFFFFFFFu, w, o);

    __shared__ float warpsum[THREADS / 32];
    if (lane == 0) warpsum[wid] = w;
    __syncthreads();

    __shared__ bool is_last;
    if (wid == 0) {
        float x = (lane < THREADS / 32) ? warpsum[lane] : 0.f;
#pragma unroll
        for (int o = 4; o > 0; o >>= 1)
            x += __shfl_down_sync(0xFFFFFFFFu, x, o);
        if (lane == 0) {
            g_partials[blockIdx.x] = (double)x;
            __threadfence();
            unsigned done = atomicAdd(&g_count, 1u);
            is_last = (done == (unsigned)(NBLOCKS - 1));
        }
    }
    __syncthreads();

    // ---- last block sums all partials in fixed index order (deterministic) ----
    if (is_last) {
        __threadfence();
        double sd = 0.0;
#pragma unroll
        for (int k = 0; k < NBLOCKS / THREADS; ++k)
            sd += g_partials[threadIdx.x + k * THREADS];
#pragma unroll
        for (int o = 16; o > 0; o >>= 1)
            sd += __shfl_down_sync(0xFFFFFFFFu, sd, o);
        __shared__ double wsum[THREADS / 32];
        if (lane == 0) wsum[wid] = sd;
        __syncthreads();
        if (wid == 0) {
            double u = (lane < THREADS / 32) ? wsum[lane] : 0.0;
#pragma unroll
            for (int o = 4; o > 0; o >>= 1)
                u += __shfl_down_sync(0xFFFFFFFFu, u, o);
            if (lane == 0) {
                d_out[0] = (float)(u / ((double)Y_ * (double)NPIX));
                g_count = 0;   // reset for next graph replay
            }
        }
    }
}

extern "C" void kernel_launch(void* const* d_in, const int* in_sizes, int n_in,
                              void* d_out, int out_size) {
    const float* out = (const float*)d_in[0];   // 'target' (d_in[1]) unused by reference
    (void)in_sizes; (void)n_in; (void)out_size;
    disturbance_loss_fused<<<NBLOCKS, THREADS>>>(out, (float*)d_out);
}